// round 5
// baseline (speedup 1.0000x reference)
#include <cuda_runtime.h>
#include <cuda_bf16.h>

#define KBINS 7
#define NBINS (KBINS * KBINS)
#define HH 1024
#define WW 1024
#define NTHREADS 256

// Scratch for cross-block reduction (no device allocs allowed).
__device__ float        g_partial[NBINS];
__device__ unsigned int g_done = 0;

__global__ __launch_bounds__(NTHREADS)
void psroi_kernel(const float* __restrict__ x,
                  const float* __restrict__ region,
                  float* __restrict__ out) {
    const int bin = blockIdx.x;          // 0..48
    const int bi  = bin / KBINS;
    const int bj  = bin - bi * KBINS;

    // ---- Replicate the reference's fp32 arithmetic exactly (no FMA fusion) ----
    const float ri = region[0], rj = region[1], rh = region[2], rw = region[3];

    const float i0 = __fsub_rn(ri, __fmul_rn(rh, 0.5f));
    const float i1 = __fadd_rn(ri, __fmul_rn(rh, 0.5f));
    const float j0 = __fsub_rn(rj, __fmul_rn(rw, 0.5f));
    const float j1 = __fadd_rn(rj, __fmul_rn(rw, 0.5f));

    // jnp.linspace(a, b, k+2): delta = (b-a)/(k+1); point t = a + t*delta.
    const float di = __fdiv_rn(__fsub_rn(i1, i0), (float)(KBINS + 1));
    const float dj = __fdiv_rn(__fsub_rn(j1, j0), (float)(KBINS + 1));
    const float ic = __fadd_rn(i0, __fmul_rn((float)(bi + 1), di));
    const float jc = __fadd_rn(j0, __fmul_rn((float)(bj + 1), dj));

    const float bh2 = __fmul_rn(__fdiv_rn(rh, (float)KBINS), 0.5f);
    const float bw2 = __fmul_rn(__fdiv_rn(rw, (float)KBINS), 0.5f);

    const float fr0 = floorf(__fmul_rn(__fsub_rn(ic, bh2), (float)HH));
    const float fr1 = ceilf (__fmul_rn(__fadd_rn(ic, bh2), (float)HH));
    const float fc0 = floorf(__fmul_rn(__fsub_rn(jc, bw2), (float)WW));
    const float fc1 = ceilf (__fmul_rn(__fadd_rn(jc, bw2), (float)WW));

    int r0 = (int)fr0; if (r0 < 0) r0 = 0;
    int r1 = (int)fr1; if (r1 > HH) r1 = HH;
    int c0 = (int)fc0; if (c0 < 0) c0 = 0;
    int c1 = (int)fc1; if (c1 > WW) c1 = WW;

    const int nr = r1 - r0;
    const int nc = c1 - c0;
    const int n  = nr * nc;               // per-bin pixel count (mask is clamped to image)

    // ---- Sum this bin's region of channel `bin` ----
    const float* __restrict__ plane = x + (size_t)bin * (size_t)HH * (size_t)WW;

    float acc = 0.0f;
    for (int t = threadIdx.x; t < n; t += NTHREADS) {
        const int r = t / nc;
        const int c = t - r * nc;
        acc += plane[(size_t)(r0 + r) * WW + (c0 + c)];
    }

    // ---- Block reduction (shfl within warp, then shared across warps) ----
    __shared__ float warp_sums[NTHREADS / 32];
    #pragma unroll
    for (int off = 16; off > 0; off >>= 1)
        acc += __shfl_down_sync(0xFFFFFFFFu, acc, off);
    const int lane = threadIdx.x & 31;
    const int wid  = threadIdx.x >> 5;
    if (lane == 0) warp_sums[wid] = acc;
    __syncthreads();

    if (threadIdx.x == 0) {
        float s = 0.0f;
        #pragma unroll
        for (int w = 0; w < NTHREADS / 32; w++) s += warp_sums[w];

        g_partial[bin] = s / (float)n;    // per-bin spatial mean

        __threadfence();                  // make g_partial[bin] visible chip-wide
        const unsigned int prev = atomicAdd(&g_done, 1u);
        if (prev == (unsigned int)gridDim.x - 1u) {
            // Last block to finish: deterministic final 49-way sum.
            float tot = 0.0f;
            #pragma unroll
            for (int b = 0; b < NBINS; b++) tot += g_partial[b];
            *out = tot / (float)NBINS;
            g_done = 0;                   // reset for next graph replay
        }
    }
}

extern "C" void kernel_launch(void* const* d_in, const int* in_sizes, int n_in,
                              void* d_out, int out_size) {
    const float* x      = (const float*)d_in[0];
    const float* region = (const float*)d_in[1];
    float*       out    = (float*)d_out;
    (void)in_sizes; (void)n_in; (void)out_size;

    psroi_kernel<<<NBINS, NTHREADS>>>(x, region, out);
}

// round 9
// speedup vs baseline: 1.2286x; 1.2286x over previous
#include <cuda_runtime.h>
#include <cuda_bf16.h>

#define KBINS 7
#define NBINS (KBINS * KBINS)
#define HH 1024
#define WW 1024
#define NTHREADS 256
#define NSLICES 6
#define NBLOCKS (NBINS * NSLICES)   // 294 CTAs -> ~2 per SM

// Scratch for cross-block reduction (no device allocs allowed).
__device__ float        g_partial[NBLOCKS];
__device__ unsigned int g_done = 0;

__global__ __launch_bounds__(NTHREADS)
void psroi_kernel(const float* __restrict__ x,
                  const float* __restrict__ region,
                  float* __restrict__ out) {
    const int bin   = blockIdx.x / NSLICES;      // 0..48
    const int slice = blockIdx.x - bin * NSLICES;
    const int bi    = bin / KBINS;
    const int bj    = bin - bi * KBINS;

    // ---- Replicate the reference's fp32 arithmetic exactly (no FMA fusion) ----
    const float ri = region[0], rj = region[1], rh = region[2], rw = region[3];

    const float i0 = __fsub_rn(ri, __fmul_rn(rh, 0.5f));
    const float i1 = __fadd_rn(ri, __fmul_rn(rh, 0.5f));
    const float j0 = __fsub_rn(rj, __fmul_rn(rw, 0.5f));
    const float j1 = __fadd_rn(rj, __fmul_rn(rw, 0.5f));

    // jnp.linspace(a, b, k+2): delta = (b-a)/(k+1); point t = a + t*delta.
    const float di = __fdiv_rn(__fsub_rn(i1, i0), (float)(KBINS + 1));
    const float dj = __fdiv_rn(__fsub_rn(j1, j0), (float)(KBINS + 1));
    const float ic = __fadd_rn(i0, __fmul_rn((float)(bi + 1), di));
    const float jc = __fadd_rn(j0, __fmul_rn((float)(bj + 1), dj));

    const float bh2 = __fmul_rn(__fdiv_rn(rh, (float)KBINS), 0.5f);
    const float bw2 = __fmul_rn(__fdiv_rn(rw, (float)KBINS), 0.5f);

    const float fr0 = floorf(__fmul_rn(__fsub_rn(ic, bh2), (float)HH));
    const float fr1 = ceilf (__fmul_rn(__fadd_rn(ic, bh2), (float)HH));
    const float fc0 = floorf(__fmul_rn(__fsub_rn(jc, bw2), (float)WW));
    const float fc1 = ceilf (__fmul_rn(__fadd_rn(jc, bw2), (float)WW));

    int r0 = (int)fr0; if (r0 < 0) r0 = 0;
    int r1 = (int)fr1; if (r1 > HH) r1 = HH;
    int c0 = (int)fc0; if (c0 < 0) c0 = 0;
    int c1 = (int)fc1; if (c1 > WW) c1 = WW;

    const int nr = r1 - r0;
    const int nc = c1 - c0;
    const int n  = nr * nc;              // full-bin pixel count (for the mean)

    // ---- This block's row slice of the bin ----
    const int rps = (nr + NSLICES - 1) / NSLICES;
    int sr0 = r0 + slice * rps;
    int sr1 = sr0 + rps; if (sr1 > r1) sr1 = r1;
    int snr = sr1 - sr0; if (snr < 0) snr = 0;
    const int m = snr * nc;              // elements handled by this block

    const float* __restrict__ plane = x + (size_t)bin * (size_t)HH * (size_t)WW;

    float acc = 0.0f;
    for (int t = threadIdx.x; t < m; t += NTHREADS) {
        const int r = t / nc;
        const int c = t - r * nc;
        acc += plane[(size_t)(sr0 + r) * WW + (c0 + c)];
    }

    // ---- Block reduction (shfl within warp, then shared across warps) ----
    __shared__ float warp_sums[NTHREADS / 32];
    __shared__ int   s_last;
    #pragma unroll
    for (int off = 16; off > 0; off >>= 1)
        acc += __shfl_down_sync(0xFFFFFFFFu, acc, off);
    const int lane = threadIdx.x & 31;
    const int wid  = threadIdx.x >> 5;
    if (lane == 0) warp_sums[wid] = acc;
    __syncthreads();

    if (threadIdx.x == 0) {
        float s = 0.0f;
        #pragma unroll
        for (int w = 0; w < NTHREADS / 32; w++) s += warp_sums[w];

        // Store slice sum pre-divided by the bin count: the global answer is
        // then a single flat fixed-order sum of all slots / NBINS.
        g_partial[blockIdx.x] = s / (float)n;

        __threadfence();                 // publish before signaling
        const unsigned int prev = atomicAdd(&g_done, 1u);
        s_last = (prev == (unsigned int)(NBLOCKS - 1)) ? 1 : 0;
    }
    __syncthreads();

    if (s_last) {
        // Last block to finish: whole block does the final 294-way sum
        // (fixed thread->slot mapping + fixed tree => deterministic).
        __threadfence();
        float a = 0.0f;
        #pragma unroll
        for (int t = threadIdx.x; t < NBLOCKS; t += NTHREADS)
            a += g_partial[t];
        #pragma unroll
        for (int off = 16; off > 0; off >>= 1)
            a += __shfl_down_sync(0xFFFFFFFFu, a, off);
        if (lane == 0) warp_sums[wid] = a;
        __syncthreads();
        if (threadIdx.x == 0) {
            float tot = 0.0f;
            #pragma unroll
            for (int w = 0; w < NTHREADS / 32; w++) tot += warp_sums[w];
            *out = tot / (float)NBINS;
            g_done = 0;                  // reset for next graph replay
        }
    }
}

extern "C" void kernel_launch(void* const* d_in, const int* in_sizes, int n_in,
                              void* d_out, int out_size) {
    const float* x      = (const float*)d_in[0];
    const float* region = (const float*)d_in[1];
    float*       out    = (float*)d_out;
    (void)in_sizes; (void)n_in; (void)out_size;

    psroi_kernel<<<NBLOCKS, NTHREADS>>>(x, region, out);
}